// round 7
// baseline (speedup 1.0000x reference)
#include <cuda_runtime.h>
#include <math.h>
#include <stdint.h>

// Problem constants
#define DIMC   128
#define NWIN   49
#define HEADS  4
#define HD     32
#define NB     4096
#define M_TOTAL (NB * NWIN)        // 200704 = 1568 * 128

// Scratch (allocation-free rule: static device globals)
__device__ float g_qkv[(size_t)NB * NWIN * 384];   // [M, 384] : q|k|v per row
__device__ float g_att[(size_t)NB * NWIN * DIMC];  // [M, 128] : attention output
__device__ float g_comb[4 * 64 * 49 * 56];         // bias+mask, [h][wm][i][j(pad56)]

__device__ __forceinline__ float to_tf32(float x) {
    float r;
    asm("cvt.rna.tf32.f32 %0, %1;" : "=f"(r) : "f"(x));
    return r;
}
// round-to-nearest tf32 as raw bits (tensor core truncates low 13 bits)
__device__ __forceinline__ uint32_t rna_bits(float x) {
    return __float_as_uint(x) + 0x1000u;
}

__device__ __forceinline__ void mma_tf32(float c[4], const uint32_t a[4],
                                         uint32_t b0, uint32_t b1) {
    asm volatile(
        "mma.sync.aligned.m16n8k8.row.col.f32.tf32.tf32.f32 "
        "{%0,%1,%2,%3}, {%4,%5,%6,%7}, {%8,%9}, {%0,%1,%2,%3};"
        : "+f"(c[0]), "+f"(c[1]), "+f"(c[2]), "+f"(c[3])
        : "r"(a[0]), "r"(a[1]), "r"(a[2]), "r"(a[3]), "r"(b0), "r"(b1));
}

#define CP_ASYNC16(dst, src) \
    asm volatile("cp.async.ca.shared.global [%0], [%1], 16;" :: "r"(dst), "l"(src))
#define CP_COMMIT() asm volatile("cp.async.commit_group;")

// ---------------------------------------------------------------------------
// tf32 GEMM v5 (occupancy-first): C[M][NC] = A[M][128] * W[NC][128]^T + bias
// Block tile 128x64, 256 threads = 8 warps (4m x 2n), warp tile 32x32
// (2x4 m16n8k8) -> 32 accumulator regs/thread -> 3-4 CTAs/SM resident.
// 3-stage cp.async ring, K chunks of 16, row stride 20 floats
// (fragment LDS.32 conflict-free). tf32 RNA applied at fragment load.
// Grid: blockIdx.x = n-tile (fastest) so n-tiles sharing an A m-tile run
// concurrently -> A re-reads come from L2, not DRAM.
// ---------------------------------------------------------------------------
#define G5_A_FLOATS (3 * 128 * 20)
#define G5_W_FLOATS (3 * 64 * 20)
#define GEMM5_SMEM ((G5_A_FLOATS + G5_W_FLOATS) * 4)   // 46080 B

template<int NC>
__global__ __launch_bounds__(256, 3) void gemm_tc5_kernel(
    const float* __restrict__ A, const float* __restrict__ W,
    const float* __restrict__ bias, float* __restrict__ C)
{
    extern __shared__ float sm[];
    float* A_s = sm;                     // [3][128][20]
    float* W_s = sm + G5_A_FLOATS;       // [3][64][20]

    const int tid  = threadIdx.x;
    const int lane = tid & 31;
    const int warp = tid >> 5;
    const int wm   = warp & 3;           // 4 warps in m
    const int wn   = warp >> 2;          // 2 warps in n
    const int g    = lane >> 2;
    const int t    = lane & 3;
    const int  n0  = blockIdx.x * 64;
    const long m0  = (long)blockIdx.y * 128;

    const uint32_t sbase = (uint32_t)__cvta_generic_to_shared(sm);
    const uint32_t wbase = sbase + G5_A_FLOATS * 4;

    // staging map: chunk = A[128x16] (512 lines) + W[64x16] (256 lines);
    // thread moves A lines {tid, tid+256} and W line {tid}.
    const int ar0 = tid >> 2, as0 = tid & 3;             // A line 1: row, seg
    const int ar1 = (tid + 256) >> 2, as1 = tid & 3;     // A line 2
    const int wr  = tid >> 2, ws = tid & 3;              // W line (tid<256 covers 64 rows x 4segs)
    const float* gA0 = A + (m0 + ar0) * 128 + as0 * 4;
    const float* gA1 = A + (m0 + ar1) * 128 + as1 * 4;
    const float* gW  = W + ((size_t)n0 + wr) * 128 + ws * 4;
    const uint32_t dA0 = sbase + (ar0 * 20 + as0 * 4) * 4;
    const uint32_t dA1 = sbase + (ar1 * 20 + as1 * 4) * 4;
    const uint32_t dW  = wbase + (wr * 20 + ws * 4) * 4;
    const uint32_t ABUF = 128 * 20 * 4;
    const uint32_t WBUF = 64 * 20 * 4;

    auto stage = [&](int kc) {
        const int buf = kc % 3;
        CP_ASYNC16(dA0 + buf * ABUF, gA0 + kc * 16);
        CP_ASYNC16(dA1 + buf * ABUF, gA1 + kc * 16);
        if (tid < 256) CP_ASYNC16(dW + buf * WBUF, gW + kc * 16);
    };

    float acc[2][4][4] = {};             // [mt][nt][frag] : warp tile 32x32

    stage(0); CP_COMMIT();
    stage(1); CP_COMMIT();

    #pragma unroll
    for (int kc = 0; kc < 8; kc++) {
        if (kc < 7) asm volatile("cp.async.wait_group 1;");
        else        asm volatile("cp.async.wait_group 0;");
        __syncthreads();
        if (kc < 6) { stage(kc + 2); CP_COMMIT(); }

        const float* Ab = A_s + (kc % 3) * 2560;
        const float* Wb = W_s + (kc % 3) * 1280;

        #pragma unroll
        for (int s = 0; s < 2; s++) {
            const int off = s * 8;
            uint32_t a[2][4];
            #pragma unroll
            for (int mt = 0; mt < 2; mt++) {
                const int r = wm * 32 + mt * 16 + g;
                a[mt][0] = rna_bits(Ab[r * 20 + off + t]);
                a[mt][1] = rna_bits(Ab[(r + 8) * 20 + off + t]);
                a[mt][2] = rna_bits(Ab[r * 20 + off + t + 4]);
                a[mt][3] = rna_bits(Ab[(r + 8) * 20 + off + t + 4]);
            }
            #pragma unroll
            for (int nt = 0; nt < 4; nt++) {
                const int n = wn * 32 + nt * 8 + g;
                uint32_t b0 = rna_bits(Wb[n * 20 + off + t]);
                uint32_t b1 = rna_bits(Wb[n * 20 + off + t + 4]);
                #pragma unroll
                for (int mt = 0; mt < 2; mt++)
                    mma_tf32(acc[mt][nt], a[mt], b0, b1);
            }
        }
    }

    #pragma unroll
    for (int nt = 0; nt < 4; nt++) {
        const int col = n0 + wn * 32 + nt * 8 + 2 * t;
        const float b0 = bias[col], b1 = bias[col + 1];
        #pragma unroll
        for (int mt = 0; mt < 2; mt++) {
            const long r = m0 + wm * 32 + mt * 16 + g;
            *(float2*)&C[r * NC + col] =
                make_float2(acc[mt][nt][0] + b0, acc[mt][nt][1] + b1);
            *(float2*)&C[(r + 8) * NC + col] =
                make_float2(acc[mt][nt][2] + b0, acc[mt][nt][3] + b1);
        }
    }
}

// ---------------------------------------------------------------------------
// Precompute combined rel-pos bias + shift mask: g_comb[h][wm][i][j(pad 56)]
// ---------------------------------------------------------------------------
__global__ void precomp_bias_mask(const float* __restrict__ mask,
                                  const float* __restrict__ bias_table,
                                  const int* __restrict__ rel_index)
{
    const int wm = blockIdx.x;   // 0..63
    const int h  = blockIdx.y;   // 0..3
    float* dst = g_comb + ((size_t)h * 64 + wm) * 49 * 56;
    for (int q = threadIdx.x; q < 49 * 56; q += blockDim.x) {
        int i = q / 56, j = q - i * 56;
        dst[q] = (j < 49)
            ? bias_table[rel_index[i * 49 + j] * HEADS + h]
              + mask[(size_t)wm * (NWIN * NWIN) + i * 49 + j]
            : -1e30f;
    }
}

// ---------------------------------------------------------------------------
// Attention (round-5 version, unchanged — known 402us-total config).
// ---------------------------------------------------------------------------
__global__ __launch_bounds__(128) void attn_tc_kernel(
    const float* __restrict__ qkv, float* __restrict__ outp)
{
    __shared__ float Qs[64][40];
    __shared__ float Ks[56][40];
    __shared__ float Vt[32][72];
    __shared__ float Ps[64][72];

    const int tid  = threadIdx.x;
    const int lane = tid & 31;
    const int warp = tid >> 5;
    const int g = lane >> 2, t = lane & 3;
    const int b = blockIdx.x >> 2, h = blockIdx.x & 3;
    const float scale = 0.17677669529663687f;   // 32^-0.5

    // ---- stage Q (scaled), K, V^T with tf32 rounding + k-interleave ----
    for (int q = tid; q < 64 * 8; q += 128) {
        int i = q >> 3, f4 = q & 7;
        int base = (f4 >> 1) * 8 + (f4 & 1);
        if (i < 49) {
            size_t row = ((size_t)b * 49 + i) * 384 + h * 32 + f4 * 4;
            float4 vq = *(const float4*)(qkv + row);
            float4 vk = *(const float4*)(qkv + row + 128);
            float4 vv = *(const float4*)(qkv + row + 256);
            Qs[i][base + 0] = to_tf32(vq.x * scale);
            Qs[i][base + 2] = to_tf32(vq.y * scale);
            Qs[i][base + 4] = to_tf32(vq.z * scale);
            Qs[i][base + 6] = to_tf32(vq.w * scale);
            Ks[i][base + 0] = to_tf32(vk.x);
            Ks[i][base + 2] = to_tf32(vk.y);
            Ks[i][base + 4] = to_tf32(vk.z);
            Ks[i][base + 6] = to_tf32(vk.w);
            int pj = (i >> 3) * 8 + 2 * (i & 3) + ((i >> 2) & 1);
            Vt[f4 * 4 + 0][pj] = to_tf32(vv.x);
            Vt[f4 * 4 + 1][pj] = to_tf32(vv.y);
            Vt[f4 * 4 + 2][pj] = to_tf32(vv.z);
            Vt[f4 * 4 + 3][pj] = to_tf32(vv.w);
        } else {
            Qs[i][base] = Qs[i][base + 2] = Qs[i][base + 4] = Qs[i][base + 6] = 0.f;
            if (i < 56) {
                Ks[i][base] = Ks[i][base + 2] = Ks[i][base + 4] = Ks[i][base + 6] = 0.f;
                int pj = (i >> 3) * 8 + 2 * (i & 3) + ((i >> 2) & 1);
                Vt[f4 * 4 + 0][pj] = 0.f;
                Vt[f4 * 4 + 1][pj] = 0.f;
                Vt[f4 * 4 + 2][pj] = 0.f;
                Vt[f4 * 4 + 3][pj] = 0.f;
            }
        }
    }

    // ---- init S accumulators from combined bias+mask (global, L2-hot) ----
    const int r0 = warp * 16 + g;
    const float* comb = g_comb + ((size_t)h * 64 + (b & 63)) * 49 * 56;
    float c[7][4];
    #pragma unroll
    for (int nt = 0; nt < 7; nt++) {
        const int col = nt * 8 + 2 * t;
        if (r0 < 49) {
            float2 f = *(const float2*)&comb[r0 * 56 + col];
            c[nt][0] = f.x; c[nt][1] = f.y;
        } else { c[nt][0] = 0.f; c[nt][1] = 0.f; }
        if (r0 + 8 < 49) {
            float2 f = *(const float2*)&comb[(r0 + 8) * 56 + col];
            c[nt][2] = f.x; c[nt][3] = f.y;
        } else { c[nt][2] = 0.f; c[nt][3] = 0.f; }
    }
    __syncthreads();

    // ---- S += (Q*scale) K^T ----
    #pragma unroll
    for (int s = 0; s < 4; s++) {
        const int off = s * 8 + 2 * t;
        uint32_t a[4];
        float2 f0 = *(const float2*)&Qs[r0][off];
        float2 f1 = *(const float2*)&Qs[r0 + 8][off];
        a[0] = __float_as_uint(f0.x); a[1] = __float_as_uint(f1.x);
        a[2] = __float_as_uint(f0.y); a[3] = __float_as_uint(f1.y);
        #pragma unroll
        for (int nt = 0; nt < 7; nt++) {
            float2 fb = *(const float2*)&Ks[nt * 8 + g][off];
            mma_tf32(c[nt], a, __float_as_uint(fb.x), __float_as_uint(fb.y));
        }
    }

    // ---- softmax in registers ----
    {
        float mx0 = -1e30f, mx1 = -1e30f;
        #pragma unroll
        for (int nt = 0; nt < 7; nt++) {
            mx0 = fmaxf(mx0, fmaxf(c[nt][0], c[nt][1]));
            mx1 = fmaxf(mx1, fmaxf(c[nt][2], c[nt][3]));
        }
        mx0 = fmaxf(mx0, __shfl_xor_sync(0xffffffffu, mx0, 1));
        mx0 = fmaxf(mx0, __shfl_xor_sync(0xffffffffu, mx0, 2));
        mx1 = fmaxf(mx1, __shfl_xor_sync(0xffffffffu, mx1, 1));
        mx1 = fmaxf(mx1, __shfl_xor_sync(0xffffffffu, mx1, 2));
        float s0 = 0.f, s1 = 0.f;
        #pragma unroll
        for (int nt = 0; nt < 7; nt++) {
            c[nt][0] = __expf(c[nt][0] - mx0);
            c[nt][1] = __expf(c[nt][1] - mx0);
            c[nt][2] = __expf(c[nt][2] - mx1);
            c[nt][3] = __expf(c[nt][3] - mx1);
            s0 += c[nt][0] + c[nt][1];
            s1 += c[nt][2] + c[nt][3];
        }
        s0 += __shfl_xor_sync(0xffffffffu, s0, 1);
        s0 += __shfl_xor_sync(0xffffffffu, s0, 2);
        s1 += __shfl_xor_sync(0xffffffffu, s1, 1);
        s1 += __shfl_xor_sync(0xffffffffu, s1, 2);
        const float i0 = 1.f / s0, i1 = 1.f / s1;

        const int pos0 = 2 * ((2 * t) & 3) + ((2 * t) >> 2);
        const int pos1 = 2 * ((2 * t + 1) & 3) + ((2 * t + 1) >> 2);
        #pragma unroll
        for (int nt = 0; nt < 7; nt++) {
            Ps[r0][nt * 8 + pos0]     = to_tf32(c[nt][0] * i0);
            Ps[r0][nt * 8 + pos1]     = to_tf32(c[nt][1] * i0);
            Ps[r0 + 8][nt * 8 + pos0] = to_tf32(c[nt][2] * i1);
            Ps[r0 + 8][nt * 8 + pos1] = to_tf32(c[nt][3] * i1);
        }
    }
    __syncwarp();

    // ---- O = P V ----
    float o[4][4];
    #pragma unroll
    for (int nt = 0; nt < 4; nt++)
        #pragma unroll
        for (int e = 0; e < 4; e++) o[nt][e] = 0.f;

    #pragma unroll
    for (int s = 0; s < 7; s++) {
        const int off = s * 8 + 2 * t;
        uint32_t a[4];
        float2 f0 = *(const float2*)&Ps[r0][off];
        float2 f1 = *(const float2*)&Ps[r0 + 8][off];
        a[0] = __float_as_uint(f0.x); a[1] = __float_as_uint(f1.x);
        a[2] = __float_as_uint(f0.y); a[3] = __float_as_uint(f1.y);
        #pragma unroll
        for (int nt = 0; nt < 4; nt++) {
            float2 fb = *(const float2*)&Vt[nt * 8 + g][off];
            mma_tf32(o[nt], a, __float_as_uint(fb.x), __float_as_uint(fb.y));
        }
    }

    #pragma unroll
    for (int nt = 0; nt < 4; nt++) {
        const int d = nt * 8 + 2 * t;
        if (r0 < 49)
            *(float2*)&outp[((size_t)b * 49 + r0) * DIMC + h * HD + d]
                = make_float2(o[nt][0], o[nt][1]);
        if (r0 + 8 < 49)
            *(float2*)&outp[((size_t)b * 49 + r0 + 8) * DIMC + h * HD + d]
                = make_float2(o[nt][2], o[nt][3]);
    }
}

// ---------------------------------------------------------------------------
extern "C" void kernel_launch(void* const* d_in, const int* in_sizes, int n_in,
                              void* d_out, int out_size)
{
    const float* x          = (const float*)d_in[0];
    const float* mask       = (const float*)d_in[1];
    const float* qkv_w      = (const float*)d_in[2];
    const float* qkv_b      = (const float*)d_in[3];
    const float* proj_w     = (const float*)d_in[4];
    const float* proj_b     = (const float*)d_in[5];
    const float* bias_table = (const float*)d_in[6];
    const int*   rel_index  = (const int*)d_in[7];
    float*       out        = (float*)d_out;

    float *qkvbuf = nullptr, *attbuf = nullptr;
    cudaGetSymbolAddress((void**)&qkvbuf, g_qkv);
    cudaGetSymbolAddress((void**)&attbuf, g_att);

    cudaFuncSetAttribute(gemm_tc5_kernel<384>,
                         cudaFuncAttributeMaxDynamicSharedMemorySize, GEMM5_SMEM);
    cudaFuncSetAttribute(gemm_tc5_kernel<DIMC>,
                         cudaFuncAttributeMaxDynamicSharedMemorySize, GEMM5_SMEM);

    dim3 gp(64, 4);
    precomp_bias_mask<<<gp, 256>>>(mask, bias_table, rel_index);

    // blockIdx.x = n-tile (fastest) -> A m-tile shared across concurrent blocks
    dim3 g1(384 / 64, M_TOTAL / 128);
    gemm_tc5_kernel<384><<<g1, 256, GEMM5_SMEM>>>(x, qkv_w, qkv_b, qkvbuf);

    attn_tc_kernel<<<NB * HEADS, 128>>>(qkvbuf, attbuf);

    dim3 g3(DIMC / 64, M_TOTAL / 128);
    gemm_tc5_kernel<DIMC><<<g3, 256, GEMM5_SMEM>>>(attbuf, proj_w, proj_b, out);
}

// round 8
// speedup vs baseline: 1.1367x; 1.1367x over previous
#include <cuda_runtime.h>
#include <math.h>
#include <stdint.h>

// Problem constants
#define DIMC   128
#define NWIN   49
#define HEADS  4
#define HD     32
#define NB     4096
#define M_TOTAL (NB * NWIN)        // 200704 = 1568 * 128

// Scratch (allocation-free rule: static device globals)
__device__ float g_qkv[(size_t)NB * NWIN * 384];   // [M, 384] : q|k|v per row
__device__ float g_att[(size_t)NB * NWIN * DIMC];  // [M, 128] : attention output
__device__ float g_comb[4 * 64 * 49 * 56];         // bias+mask, [h][wm][i][j(pad56)]

__device__ __forceinline__ float to_tf32(float x) {
    float r;
    asm("cvt.rna.tf32.f32 %0, %1;" : "=f"(r) : "f"(x));
    return r;
}
// round-to-nearest tf32 as raw bits (tensor core truncates low 13 bits)
__device__ __forceinline__ uint32_t rna_bits(float x) {
    return __float_as_uint(x) + 0x1000u;
}

__device__ __forceinline__ void mma_tf32(float c[4], const uint32_t a[4],
                                         uint32_t b0, uint32_t b1) {
    asm volatile(
        "mma.sync.aligned.m16n8k8.row.col.f32.tf32.tf32.f32 "
        "{%0,%1,%2,%3}, {%4,%5,%6,%7}, {%8,%9}, {%0,%1,%2,%3};"
        : "+f"(c[0]), "+f"(c[1]), "+f"(c[2]), "+f"(c[3])
        : "r"(a[0]), "r"(a[1]), "r"(a[2]), "r"(a[3]), "r"(b0), "r"(b1));
}

#define CP_ASYNC16(dst, src) \
    asm volatile("cp.async.ca.shared.global [%0], [%1], 16;" :: "r"(dst), "l"(src))
#define CP_COMMIT() asm volatile("cp.async.commit_group;")

// ---------------------------------------------------------------------------
// tf32 GEMM v3 (round-5 winner) with L2-friendly grid order:
// C[M][NC] = A[M][128] * W[NC][128]^T + bias
// 128x128 block tile, 8 warps (2m x 4n), warp tile 64x32, K chunks of 16.
// 3-stage cp.async ring, ONE __syncthreads per chunk. Row stride 20 floats.
// blockIdx.x = n-tile (fastest, only NC/128 values) so all n-tiles of an
// m-tile are co-resident -> A re-reads hit L2 instead of DRAM.
// ---------------------------------------------------------------------------
#define GEMM_SMEM_BYTES (6 * 128 * 20 * 4)   // 3 bufs x (A + W)

template<int NC>
__global__ __launch_bounds__(256, 2) void gemm_tc3_kernel(
    const float* __restrict__ A, const float* __restrict__ W,
    const float* __restrict__ bias, float* __restrict__ C)
{
    extern __shared__ float sm[];            // [3][128][20] A, then [3][128][20] W

    const int tid  = threadIdx.x;
    const int lane = tid & 31;
    const int warp = tid >> 5;
    const int wm   = warp & 1;
    const int wn   = warp >> 1;
    const int g    = lane >> 2;
    const int t    = lane & 3;
    const long m0  = (long)blockIdx.y * 128;
    const int  n0  = blockIdx.x * 128;

    const int srow = tid >> 2;               // 0..63
    const int sf   = tid & 3;
    const float* gA = A + (m0 + srow) * 128 + sf * 4;
    const float* gW = W + ((size_t)n0 + srow) * 128 + sf * 4;
    const uint32_t sbase = (uint32_t)__cvta_generic_to_shared(sm);
    const uint32_t sA = sbase + (srow * 20 + sf * 4) * 4;
    const uint32_t sW = sA + 3 * 10240;
    const uint32_t BUFB  = 10240;            // 128*20*4
    const uint32_t ROW64 = 64 * 20 * 4;

    auto stage = [&](int kc, int buf) {
        const float* a = gA + kc * 16;
        const float* w = gW + kc * 16;
        CP_ASYNC16(sA + buf * BUFB,         a);
        CP_ASYNC16(sA + buf * BUFB + ROW64, a + 64 * 128);
        CP_ASYNC16(sW + buf * BUFB,         w);
        CP_ASYNC16(sW + buf * BUFB + ROW64, w + 64 * 128);
    };

    float acc[4][4][4] = {};

    stage(0, 0); CP_COMMIT();
    stage(1, 1); CP_COMMIT();

    #pragma unroll
    for (int kc = 0; kc < 8; kc++) {
        if (kc < 7) asm volatile("cp.async.wait_group 1;");
        else        asm volatile("cp.async.wait_group 0;");
        __syncthreads();
        if (kc < 6) { stage(kc + 2, (kc + 2) % 3); CP_COMMIT(); }

        const float* Ab = sm + (kc % 3) * 2560;
        const float* Wb = Ab + 3 * 2560;

        #pragma unroll
        for (int s = 0; s < 2; s++) {
            const int off = s * 8;
            uint32_t a[4][4];
            #pragma unroll
            for (int mt = 0; mt < 4; mt++) {
                int r = wm * 64 + mt * 16 + g;
                a[mt][0] = rna_bits(Ab[r * 20 + off + t]);
                a[mt][1] = rna_bits(Ab[(r + 8) * 20 + off + t]);
                a[mt][2] = rna_bits(Ab[r * 20 + off + t + 4]);
                a[mt][3] = rna_bits(Ab[(r + 8) * 20 + off + t + 4]);
            }
            #pragma unroll
            for (int nt = 0; nt < 4; nt++) {
                int n = wn * 32 + nt * 8 + g;
                uint32_t b0 = rna_bits(Wb[n * 20 + off + t]);
                uint32_t b1 = rna_bits(Wb[n * 20 + off + t + 4]);
                #pragma unroll
                for (int mt = 0; mt < 4; mt++)
                    mma_tf32(acc[mt][nt], a[mt], b0, b1);
            }
        }
    }

    #pragma unroll
    for (int nt = 0; nt < 4; nt++) {
        int col = n0 + wn * 32 + nt * 8 + 2 * t;
        float b0 = bias[col], b1 = bias[col + 1];
        #pragma unroll
        for (int mt = 0; mt < 4; mt++) {
            long r = m0 + wm * 64 + mt * 16 + g;
            *(float2*)&C[r * NC + col] =
                make_float2(acc[mt][nt][0] + b0, acc[mt][nt][1] + b1);
            *(float2*)&C[(r + 8) * NC + col] =
                make_float2(acc[mt][nt][2] + b0, acc[mt][nt][3] + b1);
        }
    }
}

// ---------------------------------------------------------------------------
// Precompute combined rel-pos bias + shift mask: g_comb[h][wm][i][j(pad 56)]
// ---------------------------------------------------------------------------
__global__ void precomp_bias_mask(const float* __restrict__ mask,
                                  const float* __restrict__ bias_table,
                                  const int* __restrict__ rel_index)
{
    const int wm = blockIdx.x;   // 0..63
    const int h  = blockIdx.y;   // 0..3
    float* dst = g_comb + ((size_t)h * 64 + wm) * 49 * 56;
    for (int q = threadIdx.x; q < 49 * 56; q += blockDim.x) {
        int i = q / 56, j = q - i * 56;
        dst[q] = (j < 49)
            ? bias_table[rel_index[i * 49 + j] * HEADS + h]
              + mask[(size_t)wm * (NWIN * NWIN) + i * 49 + j]
            : -1e30f;
    }
}

// ---------------------------------------------------------------------------
// Attention (round-5 version, unchanged — known-good 157us config).
// ---------------------------------------------------------------------------
__global__ __launch_bounds__(128) void attn_tc_kernel(
    const float* __restrict__ qkv, float* __restrict__ outp)
{
    __shared__ float Qs[64][40];
    __shared__ float Ks[56][40];
    __shared__ float Vt[32][72];
    __shared__ float Ps[64][72];

    const int tid  = threadIdx.x;
    const int lane = tid & 31;
    const int warp = tid >> 5;
    const int g = lane >> 2, t = lane & 3;
    const int b = blockIdx.x >> 2, h = blockIdx.x & 3;
    const float scale = 0.17677669529663687f;   // 32^-0.5

    // ---- stage Q (scaled), K, V^T with tf32 rounding + k-interleave ----
    for (int q = tid; q < 64 * 8; q += 128) {
        int i = q >> 3, f4 = q & 7;
        int base = (f4 >> 1) * 8 + (f4 & 1);
        if (i < 49) {
            size_t row = ((size_t)b * 49 + i) * 384 + h * 32 + f4 * 4;
            float4 vq = *(const float4*)(qkv + row);
            float4 vk = *(const float4*)(qkv + row + 128);
            float4 vv = *(const float4*)(qkv + row + 256);
            Qs[i][base + 0] = to_tf32(vq.x * scale);
            Qs[i][base + 2] = to_tf32(vq.y * scale);
            Qs[i][base + 4] = to_tf32(vq.z * scale);
            Qs[i][base + 6] = to_tf32(vq.w * scale);
            Ks[i][base + 0] = to_tf32(vk.x);
            Ks[i][base + 2] = to_tf32(vk.y);
            Ks[i][base + 4] = to_tf32(vk.z);
            Ks[i][base + 6] = to_tf32(vk.w);
            int pj = (i >> 3) * 8 + 2 * (i & 3) + ((i >> 2) & 1);
            Vt[f4 * 4 + 0][pj] = to_tf32(vv.x);
            Vt[f4 * 4 + 1][pj] = to_tf32(vv.y);
            Vt[f4 * 4 + 2][pj] = to_tf32(vv.z);
            Vt[f4 * 4 + 3][pj] = to_tf32(vv.w);
        } else {
            Qs[i][base] = Qs[i][base + 2] = Qs[i][base + 4] = Qs[i][base + 6] = 0.f;
            if (i < 56) {
                Ks[i][base] = Ks[i][base + 2] = Ks[i][base + 4] = Ks[i][base + 6] = 0.f;
                int pj = (i >> 3) * 8 + 2 * (i & 3) + ((i >> 2) & 1);
                Vt[f4 * 4 + 0][pj] = 0.f;
                Vt[f4 * 4 + 1][pj] = 0.f;
                Vt[f4 * 4 + 2][pj] = 0.f;
                Vt[f4 * 4 + 3][pj] = 0.f;
            }
        }
    }

    // ---- init S accumulators from combined bias+mask (global, L2-hot) ----
    const int r0 = warp * 16 + g;
    const float* comb = g_comb + ((size_t)h * 64 + (b & 63)) * 49 * 56;
    float c[7][4];
    #pragma unroll
    for (int nt = 0; nt < 7; nt++) {
        const int col = nt * 8 + 2 * t;
        if (r0 < 49) {
            float2 f = *(const float2*)&comb[r0 * 56 + col];
            c[nt][0] = f.x; c[nt][1] = f.y;
        } else { c[nt][0] = 0.f; c[nt][1] = 0.f; }
        if (r0 + 8 < 49) {
            float2 f = *(const float2*)&comb[(r0 + 8) * 56 + col];
            c[nt][2] = f.x; c[nt][3] = f.y;
        } else { c[nt][2] = 0.f; c[nt][3] = 0.f; }
    }
    __syncthreads();

    // ---- S += (Q*scale) K^T ----
    #pragma unroll
    for (int s = 0; s < 4; s++) {
        const int off = s * 8 + 2 * t;
        uint32_t a[4];
        float2 f0 = *(const float2*)&Qs[r0][off];
        float2 f1 = *(const float2*)&Qs[r0 + 8][off];
        a[0] = __float_as_uint(f0.x); a[1] = __float_as_uint(f1.x);
        a[2] = __float_as_uint(f0.y); a[3] = __float_as_uint(f1.y);
        #pragma unroll
        for (int nt = 0; nt < 7; nt++) {
            float2 fb = *(const float2*)&Ks[nt * 8 + g][off];
            mma_tf32(c[nt], a, __float_as_uint(fb.x), __float_as_uint(fb.y));
        }
    }

    // ---- softmax in registers ----
    {
        float mx0 = -1e30f, mx1 = -1e30f;
        #pragma unroll
        for (int nt = 0; nt < 7; nt++) {
            mx0 = fmaxf(mx0, fmaxf(c[nt][0], c[nt][1]));
            mx1 = fmaxf(mx1, fmaxf(c[nt][2], c[nt][3]));
        }
        mx0 = fmaxf(mx0, __shfl_xor_sync(0xffffffffu, mx0, 1));
        mx0 = fmaxf(mx0, __shfl_xor_sync(0xffffffffu, mx0, 2));
        mx1 = fmaxf(mx1, __shfl_xor_sync(0xffffffffu, mx1, 1));
        mx1 = fmaxf(mx1, __shfl_xor_sync(0xffffffffu, mx1, 2));
        float s0 = 0.f, s1 = 0.f;
        #pragma unroll
        for (int nt = 0; nt < 7; nt++) {
            c[nt][0] = __expf(c[nt][0] - mx0);
            c[nt][1] = __expf(c[nt][1] - mx0);
            c[nt][2] = __expf(c[nt][2] - mx1);
            c[nt][3] = __expf(c[nt][3] - mx1);
            s0 += c[nt][0] + c[nt][1];
            s1 += c[nt][2] + c[nt][3];
        }
        s0 += __shfl_xor_sync(0xffffffffu, s0, 1);
        s0 += __shfl_xor_sync(0xffffffffu, s0, 2);
        s1 += __shfl_xor_sync(0xffffffffu, s1, 1);
        s1 += __shfl_xor_sync(0xffffffffu, s1, 2);
        const float i0 = 1.f / s0, i1 = 1.f / s1;

        const int pos0 = 2 * ((2 * t) & 3) + ((2 * t) >> 2);
        const int pos1 = 2 * ((2 * t + 1) & 3) + ((2 * t + 1) >> 2);
        #pragma unroll
        for (int nt = 0; nt < 7; nt++) {
            Ps[r0][nt * 8 + pos0]     = to_tf32(c[nt][0] * i0);
            Ps[r0][nt * 8 + pos1]     = to_tf32(c[nt][1] * i0);
            Ps[r0 + 8][nt * 8 + pos0] = to_tf32(c[nt][2] * i1);
            Ps[r0 + 8][nt * 8 + pos1] = to_tf32(c[nt][3] * i1);
        }
    }
    __syncwarp();

    // ---- O = P V ----
    float o[4][4];
    #pragma unroll
    for (int nt = 0; nt < 4; nt++)
        #pragma unroll
        for (int e = 0; e < 4; e++) o[nt][e] = 0.f;

    #pragma unroll
    for (int s = 0; s < 7; s++) {
        const int off = s * 8 + 2 * t;
        uint32_t a[4];
        float2 f0 = *(const float2*)&Ps[r0][off];
        float2 f1 = *(const float2*)&Ps[r0 + 8][off];
        a[0] = __float_as_uint(f0.x); a[1] = __float_as_uint(f1.x);
        a[2] = __float_as_uint(f0.y); a[3] = __float_as_uint(f1.y);
        #pragma unroll
        for (int nt = 0; nt < 4; nt++) {
            float2 fb = *(const float2*)&Vt[nt * 8 + g][off];
            mma_tf32(o[nt], a, __float_as_uint(fb.x), __float_as_uint(fb.y));
        }
    }

    #pragma unroll
    for (int nt = 0; nt < 4; nt++) {
        const int d = nt * 8 + 2 * t;
        if (r0 < 49)
            *(float2*)&outp[((size_t)b * 49 + r0) * DIMC + h * HD + d]
                = make_float2(o[nt][0], o[nt][1]);
        if (r0 + 8 < 49)
            *(float2*)&outp[((size_t)b * 49 + r0 + 8) * DIMC + h * HD + d]
                = make_float2(o[nt][2], o[nt][3]);
    }
}

// ---------------------------------------------------------------------------
extern "C" void kernel_launch(void* const* d_in, const int* in_sizes, int n_in,
                              void* d_out, int out_size)
{
    const float* x          = (const float*)d_in[0];
    const float* mask       = (const float*)d_in[1];
    const float* qkv_w      = (const float*)d_in[2];
    const float* qkv_b      = (const float*)d_in[3];
    const float* proj_w     = (const float*)d_in[4];
    const float* proj_b     = (const float*)d_in[5];
    const float* bias_table = (const float*)d_in[6];
    const int*   rel_index  = (const int*)d_in[7];
    float*       out        = (float*)d_out;

    float *qkvbuf = nullptr, *attbuf = nullptr;
    cudaGetSymbolAddress((void**)&qkvbuf, g_qkv);
    cudaGetSymbolAddress((void**)&attbuf, g_att);

    cudaFuncSetAttribute(gemm_tc3_kernel<384>,
                         cudaFuncAttributeMaxDynamicSharedMemorySize, GEMM_SMEM_BYTES);
    cudaFuncSetAttribute(gemm_tc3_kernel<DIMC>,
                         cudaFuncAttributeMaxDynamicSharedMemorySize, GEMM_SMEM_BYTES);

    dim3 gp(64, 4);
    precomp_bias_mask<<<gp, 256>>>(mask, bias_table, rel_index);

    // n-tile fastest: the 3 n-tiles of an m-tile run concurrently (A via L2)
    dim3 g1(384 / 128, M_TOTAL / 128);
    gemm_tc3_kernel<384><<<g1, 256, GEMM_SMEM_BYTES>>>(x, qkv_w, qkv_b, qkvbuf);

    attn_tc_kernel<<<NB * HEADS, 128>>>(qkvbuf, attbuf);

    dim3 g3(DIMC / 128, M_TOTAL / 128);
    gemm_tc3_kernel<DIMC><<<g3, 256, GEMM_SMEM_BYTES>>>(attbuf, proj_w, proj_b, out);
}